// round 1
// baseline (speedup 1.0000x reference)
#include <cuda_runtime.h>
#include <math.h>

#define N_NODES 20000
#define K_IN    8710
#define H_DIM   128
#define C_DIM   70

// ---- scratch (static device globals; no allocation allowed) ----
__device__ float g_h[(size_t)N_NODES * H_DIM];    // x@W1, then relu(agg+b1)
__device__ float g_agg[(size_t)N_NODES * H_DIM];  // layer-1 aggregation
__device__ float g_z[(size_t)N_NODES * C_DIM];    // h1@W2
__device__ int   g_deg[N_NODES];
__device__ float g_dinv[N_NODES];

// ---------------------------------------------------------------------------
// degree / normalization
// ---------------------------------------------------------------------------
__global__ void k_zero_deg() {
    int i = blockIdx.x * blockDim.x + threadIdx.x;
    if (i < N_NODES) g_deg[i] = 0;
}

__global__ void k_count_deg(const int* __restrict__ edges, int E) {
    int e = blockIdx.x * blockDim.x + threadIdx.x;
    if (e < E) atomicAdd(&g_deg[edges[E + e]], 1);   // dst
}

__global__ void k_dinv() {
    int i = blockIdx.x * blockDim.x + threadIdx.x;
    if (i < N_NODES) g_dinv[i] = rsqrtf((float)(g_deg[i] + 1));  // +1 self loop
}

// ---------------------------------------------------------------------------
// GEMM1: h = x @ W1   [20000 x 8710] @ [8710 x 128]
// BM=128, BN=64, BK=16, 256 threads, 8x4 register tile per thread
// ---------------------------------------------------------------------------
__global__ __launch_bounds__(256) void k_gemm1(const float* __restrict__ X,
                                               const float* __restrict__ W) {
    __shared__ float As[16][128];
    __shared__ float Bs[16][64];

    const int tid = threadIdx.x;
    const int m0 = blockIdx.x * 128;
    const int n0 = blockIdx.y * 64;
    const int tx = tid & 15;       // col group (0..15)
    const int ty = tid >> 4;       // row group (0..15)
    const int row = ty * 8;
    const int col = tx * 4;

    float acc[8][4];
#pragma unroll
    for (int i = 0; i < 8; i++)
#pragma unroll
        for (int j = 0; j < 4; j++) acc[i][j] = 0.f;

    for (int k0 = 0; k0 < K_IN; k0 += 16) {
        // load A tile (128 x 16) as float2 (x rows are only 8B aligned: 8710 % 4 == 2)
#pragma unroll
        for (int f = 0; f < 4; f++) {
            int idx = tid + f * 256;        // 0..1023 float2 slots
            int ar = idx >> 3;              // row in tile
            int ac = (idx & 7) * 2;         // k in tile (even)
            int gm = m0 + ar;
            int gk = k0 + ac;
            float2 v = make_float2(0.f, 0.f);
            if (gm < N_NODES && gk + 1 < K_IN) {
                v = *reinterpret_cast<const float2*>(X + (size_t)gm * K_IN + gk);
            } else if (gm < N_NODES && gk < K_IN) {
                v.x = X[(size_t)gm * K_IN + gk];
            }
            As[ac][ar]     = v.x;
            As[ac + 1][ar] = v.y;
        }
        // load B tile (16 x 64) as float4 (W1 rows are 512B aligned)
        {
            int br = tid >> 4;
            int bc = (tid & 15) * 4;
            int gk = k0 + br;
            float4 v = make_float4(0.f, 0.f, 0.f, 0.f);
            if (gk < K_IN)
                v = *reinterpret_cast<const float4*>(W + (size_t)gk * H_DIM + n0 + bc);
            *reinterpret_cast<float4*>(&Bs[br][bc]) = v;
        }
        __syncthreads();

#pragma unroll
        for (int kk = 0; kk < 16; kk++) {
            float a[8], b[4];
#pragma unroll
            for (int i = 0; i < 8; i++) a[i] = As[kk][row + i];
#pragma unroll
            for (int j = 0; j < 4; j++) b[j] = Bs[kk][col + j];
#pragma unroll
            for (int i = 0; i < 8; i++)
#pragma unroll
                for (int j = 0; j < 4; j++) acc[i][j] += a[i] * b[j];
        }
        __syncthreads();
    }

#pragma unroll
    for (int i = 0; i < 8; i++) {
        int gm = m0 + row + i;
        if (gm < N_NODES) {
#pragma unroll
            for (int j = 0; j < 4; j++)
                g_h[(size_t)gm * H_DIM + n0 + col + j] = acc[i][j];
        }
    }
}

// ---------------------------------------------------------------------------
// layer-1 aggregation
// ---------------------------------------------------------------------------
__global__ void k_agg1_init() {   // self-loop term, full overwrite
    int idx = blockIdx.x * blockDim.x + threadIdx.x;   // N*32 float4 slots
    if (idx >= N_NODES * 32) return;
    int n = idx >> 5;
    float s = g_dinv[n]; s = s * s;
    float4 v = *reinterpret_cast<const float4*>(g_h + (size_t)idx * 4);
    v.x *= s; v.y *= s; v.z *= s; v.w *= s;
    *reinterpret_cast<float4*>(g_agg + (size_t)idx * 4) = v;
}

__global__ void k_scatter1(const int* __restrict__ edges, int E) {
    int idx = blockIdx.x * blockDim.x + threadIdx.x;   // E*32 (edge, col4)
    if (idx >= E * 32) return;
    int e = idx >> 5;
    int g = idx & 31;
    int s = edges[e];
    int d = edges[E + e];
    float norm = g_dinv[s] * g_dinv[d];
    float4 v = *reinterpret_cast<const float4*>(g_h + (size_t)s * H_DIM + g * 4);
    float* p = g_agg + (size_t)d * H_DIM + g * 4;
    atomicAdd(p + 0, v.x * norm);
    atomicAdd(p + 1, v.y * norm);
    atomicAdd(p + 2, v.z * norm);
    atomicAdd(p + 3, v.w * norm);
}

__global__ void k_bias_relu(const float* __restrict__ b1) {
    int idx = blockIdx.x * blockDim.x + threadIdx.x;   // N*32 float4 slots
    if (idx >= N_NODES * 32) return;
    int j4 = (idx & 31) * 4;
    float4 b = *reinterpret_cast<const float4*>(b1 + j4);
    float4 v = *reinterpret_cast<const float4*>(g_agg + (size_t)idx * 4);
    v.x = fmaxf(v.x + b.x, 0.f);
    v.y = fmaxf(v.y + b.y, 0.f);
    v.z = fmaxf(v.z + b.z, 0.f);
    v.w = fmaxf(v.w + b.w, 0.f);
    *reinterpret_cast<float4*>(g_h + (size_t)idx * 4) = v;
}

// ---------------------------------------------------------------------------
// GEMM2: z = h1 @ W2   [20000 x 128] @ [128 x 70] — warp per row
// ---------------------------------------------------------------------------
__global__ __launch_bounds__(256) void k_gemm2(const float* __restrict__ W2) {
    __shared__ float W2s[H_DIM * C_DIM];   // 35840 B
    int tid = threadIdx.x;
    for (int i = tid; i < H_DIM * C_DIM; i += 256) W2s[i] = W2[i];
    __syncthreads();

    int warp = tid >> 5, lane = tid & 31;
    int n = blockIdx.x * 8 + warp;
    if (n >= N_NODES) return;
    const float* hr = g_h + (size_t)n * H_DIM;

    float a0 = 0.f, a1 = 0.f, a2 = 0.f;
#pragma unroll 4
    for (int k = 0; k < H_DIM; k++) {
        float hv = __ldg(hr + k);                  // uniform per warp
        const float* wr = W2s + k * C_DIM;
        a0 += hv * wr[lane];
        a1 += hv * wr[lane + 32];
        if (lane < C_DIM - 64) a2 += hv * wr[lane + 64];
    }
    float* zr = g_z + (size_t)n * C_DIM;
    zr[lane]      = a0;
    zr[lane + 32] = a1;
    if (lane < C_DIM - 64) zr[lane + 64] = a2;
}

// ---------------------------------------------------------------------------
// layer-2 aggregation (into d_out) + softmax
// ---------------------------------------------------------------------------
__global__ void k_agg2_init(float* __restrict__ out) {
    int idx = blockIdx.x * blockDim.x + threadIdx.x;   // N*70
    if (idx >= N_NODES * C_DIM) return;
    int n = idx / C_DIM;
    float s = g_dinv[n]; s = s * s;
    out[idx] = g_z[idx] * s;
}

__global__ void k_scatter2(const int* __restrict__ edges, int E,
                           float* __restrict__ out) {
    int idx = blockIdx.x * blockDim.x + threadIdx.x;   // E*70
    if (idx >= E * C_DIM) return;
    int e = idx / C_DIM;
    int c = idx - e * C_DIM;
    int s = edges[e];
    int d = edges[E + e];
    float norm = g_dinv[s] * g_dinv[d];
    atomicAdd(&out[(size_t)d * C_DIM + c], g_z[(size_t)s * C_DIM + c] * norm);
}

__global__ __launch_bounds__(256) void k_softmax(const float* __restrict__ b2,
                                                 float* __restrict__ out) {
    int warp = threadIdx.x >> 5, lane = threadIdx.x & 31;
    int n = blockIdx.x * 8 + warp;
    if (n >= N_NODES) return;
    float* r = out + (size_t)n * C_DIM;

    float v0 = r[lane] + b2[lane];
    float v1 = r[lane + 32] + b2[lane + 32];
    float v2 = (lane < C_DIM - 64) ? r[lane + 64] + b2[lane + 64] : -INFINITY;

    float m = fmaxf(fmaxf(v0, v1), v2);
#pragma unroll
    for (int o = 16; o > 0; o >>= 1) m = fmaxf(m, __shfl_xor_sync(0xffffffff, m, o));

    float e0 = expf(v0 - m);
    float e1 = expf(v1 - m);
    float e2 = (lane < C_DIM - 64) ? expf(v2 - m) : 0.f;
    float s = e0 + e1 + e2;
#pragma unroll
    for (int o = 16; o > 0; o >>= 1) s += __shfl_xor_sync(0xffffffff, s, o);
    float inv = 1.f / s;

    r[lane]      = e0 * inv;
    r[lane + 32] = e1 * inv;
    if (lane < C_DIM - 64) r[lane + 64] = e2 * inv;
}

// ---------------------------------------------------------------------------
extern "C" void kernel_launch(void* const* d_in, const int* in_sizes, int n_in,
                              void* d_out, int out_size) {
    const float* x  = (const float*)d_in[0];
    const int* edges = (const int*)d_in[1];
    const float* W1 = (const float*)d_in[2];
    const float* b1 = (const float*)d_in[3];
    const float* W2 = (const float*)d_in[4];
    const float* b2 = (const float*)d_in[5];
    float* out = (float*)d_out;
    const int E = in_sizes[1] / 2;

    // degree / dinv
    k_zero_deg<<<(N_NODES + 255) / 256, 256>>>();
    k_count_deg<<<(E + 255) / 256, 256>>>(edges, E);
    k_dinv<<<(N_NODES + 255) / 256, 256>>>();

    // layer 1
    dim3 g1((N_NODES + 127) / 128, H_DIM / 64);
    k_gemm1<<<g1, 256>>>(x, W1);
    k_agg1_init<<<(N_NODES * 32 + 255) / 256, 256>>>();
    k_scatter1<<<(E * 32 + 255) / 256, 256>>>(edges, E);
    k_bias_relu<<<(N_NODES * 32 + 255) / 256, 256>>>(b1);

    // layer 2
    k_gemm2<<<(N_NODES + 7) / 8, 256>>>(W2);
    k_agg2_init<<<(N_NODES * C_DIM + 255) / 256, 256>>>(out);
    k_scatter2<<<(E * C_DIM + 255) / 256, 256>>>(edges, E, out);
    k_softmax<<<(N_NODES + 7) / 8, 256>>>(b2, out);
}

// round 2
// speedup vs baseline: 2.4868x; 2.4868x over previous
#include <cuda_runtime.h>
#include <math.h>

#define N_NODES 20000
#define K_IN    8710
#define H_DIM   128
#define C_DIM   70

// ---- scratch (static device globals; no allocation allowed) ----
__device__ float g_h[(size_t)N_NODES * H_DIM];    // x@W1, then relu(agg+b1)
__device__ float g_agg[(size_t)N_NODES * H_DIM];  // layer-1 aggregation
__device__ float g_z[(size_t)N_NODES * C_DIM];    // h1@W2
__device__ int   g_deg[N_NODES];
__device__ float g_dinv[N_NODES];

// ---------------------------------------------------------------------------
// degree / normalization
// ---------------------------------------------------------------------------
__global__ void k_zero_deg() {
    int i = blockIdx.x * blockDim.x + threadIdx.x;
    if (i < N_NODES) g_deg[i] = 0;
}

__global__ void k_count_deg(const int* __restrict__ edges, int E) {
    int e = blockIdx.x * blockDim.x + threadIdx.x;
    if (e < E) atomicAdd(&g_deg[edges[E + e]], 1);   // dst
}

__global__ void k_dinv() {
    int i = blockIdx.x * blockDim.x + threadIdx.x;
    if (i < N_NODES) g_dinv[i] = rsqrtf((float)(g_deg[i] + 1));  // +1 self loop
}

// ---------------------------------------------------------------------------
// GEMM1 on tensor cores: h = x @ W1  [20000 x 8710] @ [8710 x 128], tf32 HMMA
// BM=64, BN=128, BK=16, 128 threads = 4 warps (2x2), warp tile 32x64
// ---------------------------------------------------------------------------
#define NC_CHUNKS ((K_IN + 15) / 16)   // 545

__device__ __forceinline__ unsigned f2tf(float f) {
    unsigned u;
    asm("cvt.rna.tf32.f32 %0, %1;" : "=r"(u) : "f"(f));
    return u;
}

__global__ __launch_bounds__(128) void k_gemm1_tc(const float* __restrict__ X,
                                                  const float* __restrict__ W) {
    __shared__ unsigned As[2][64][18];    // [buf][m][k], pad to 18
    __shared__ unsigned Bs[2][16][132];   // [buf][k][n], pad to 132

    const int tid  = threadIdx.x;
    const int warp = tid >> 5;
    const int lane = tid & 31;
    const int gid  = lane >> 2;   // group id 0..7
    const int tig  = lane & 3;    // thread-in-group 0..3
    const int warp_m = warp >> 1;     // 0..1
    const int warp_n = warp & 1;      // 0..1
    const int m0 = blockIdx.x * 64;

    float acc[2][8][4];
#pragma unroll
    for (int i = 0; i < 2; i++)
#pragma unroll
        for (int j = 0; j < 8; j++)
#pragma unroll
            for (int t = 0; t < 4; t++) acc[i][j][t] = 0.f;

    float2 ra[4];
    float4 rb[4];

    // ---- staging helpers (inlined manually) ----
    // A: 64x16 = 512 float2 slots; B: 16x128 = 512 float4 slots
#define LOAD_GLOBAL(k0)                                                          \
    {                                                                            \
        _Pragma("unroll")                                                        \
        for (int i = 0; i < 4; i++) {                                            \
            int slot = tid + i * 128;                                            \
            int row  = slot >> 3;                                                \
            int kp   = (slot & 7) * 2;                                           \
            int gm = m0 + row, gk = (k0) + kp;                                   \
            float2 v = make_float2(0.f, 0.f);                                    \
            if (gm < N_NODES && gk + 1 < K_IN)                                   \
                v = *reinterpret_cast<const float2*>(X + (size_t)gm * K_IN + gk);\
            else if (gm < N_NODES && gk < K_IN)                                  \
                v.x = X[(size_t)gm * K_IN + gk];                                 \
            ra[i] = v;                                                           \
        }                                                                        \
        _Pragma("unroll")                                                        \
        for (int i = 0; i < 4; i++) {                                            \
            int slot = tid + i * 128;                                            \
            int kr   = slot >> 5;                                                \
            int nc   = (slot & 31) * 4;                                          \
            int gk = (k0) + kr;                                                  \
            float4 v = make_float4(0.f, 0.f, 0.f, 0.f);                          \
            if (gk < K_IN)                                                       \
                v = *reinterpret_cast<const float4*>(W + (size_t)gk * H_DIM + nc);\
            rb[i] = v;                                                           \
        }                                                                        \
    }

#define STORE_SMEM(buf)                                                          \
    {                                                                            \
        _Pragma("unroll")                                                        \
        for (int i = 0; i < 4; i++) {                                            \
            int slot = tid + i * 128;                                            \
            int row  = slot >> 3;                                                \
            int kp   = (slot & 7) * 2;                                           \
            As[buf][row][kp]     = f2tf(ra[i].x);                                \
            As[buf][row][kp + 1] = f2tf(ra[i].y);                                \
        }                                                                        \
        _Pragma("unroll")                                                        \
        for (int i = 0; i < 4; i++) {                                            \
            int slot = tid + i * 128;                                            \
            int kr   = slot >> 5;                                                \
            int nc   = (slot & 31) * 4;                                          \
            Bs[buf][kr][nc]     = f2tf(rb[i].x);                                 \
            Bs[buf][kr][nc + 1] = f2tf(rb[i].y);                                 \
            Bs[buf][kr][nc + 2] = f2tf(rb[i].z);                                 \
            Bs[buf][kr][nc + 3] = f2tf(rb[i].w);                                 \
        }                                                                        \
    }

    LOAD_GLOBAL(0);
    STORE_SMEM(0);
    __syncthreads();

    for (int c = 0; c < NC_CHUNKS; ++c) {
        const int cur = c & 1;
        if (c + 1 < NC_CHUNKS) LOAD_GLOBAL((c + 1) * 16);

        // compute 2 k-steps of 8 from smem[cur]
#pragma unroll
        for (int ks = 0; ks < 2; ks++) {
            const int kb = ks * 8;
            unsigned af[2][4];
#pragma unroll
            for (int mt = 0; mt < 2; mt++) {
                int rb_ = warp_m * 32 + mt * 16 + gid;
                af[mt][0] = As[cur][rb_][kb + tig];
                af[mt][1] = As[cur][rb_ + 8][kb + tig];
                af[mt][2] = As[cur][rb_][kb + tig + 4];
                af[mt][3] = As[cur][rb_ + 8][kb + tig + 4];
            }
            unsigned bf[8][2];
#pragma unroll
            for (int nt = 0; nt < 8; nt++) {
                int nb = warp_n * 64 + nt * 8 + gid;
                bf[nt][0] = Bs[cur][kb + tig][nb];
                bf[nt][1] = Bs[cur][kb + tig + 4][nb];
            }
#pragma unroll
            for (int mt = 0; mt < 2; mt++)
#pragma unroll
                for (int nt = 0; nt < 8; nt++) {
                    asm volatile(
                        "mma.sync.aligned.m16n8k8.row.col.f32.tf32.tf32.f32 "
                        "{%0,%1,%2,%3}, {%4,%5,%6,%7}, {%8,%9}, {%0,%1,%2,%3};"
                        : "+f"(acc[mt][nt][0]), "+f"(acc[mt][nt][1]),
                          "+f"(acc[mt][nt][2]), "+f"(acc[mt][nt][3])
                        : "r"(af[mt][0]), "r"(af[mt][1]), "r"(af[mt][2]), "r"(af[mt][3]),
                          "r"(bf[nt][0]), "r"(bf[nt][1]));
                }
        }

        if (c + 1 < NC_CHUNKS) {
            STORE_SMEM((c + 1) & 1);
        }
        __syncthreads();
    }

    // epilogue: write accumulators to g_h
#pragma unroll
    for (int mt = 0; mt < 2; mt++) {
        int r0 = m0 + warp_m * 32 + mt * 16 + gid;
        int r1 = r0 + 8;
#pragma unroll
        for (int nt = 0; nt < 8; nt++) {
            int col = warp_n * 64 + nt * 8 + tig * 2;
            if (r0 < N_NODES)
                *reinterpret_cast<float2*>(g_h + (size_t)r0 * H_DIM + col) =
                    make_float2(acc[mt][nt][0], acc[mt][nt][1]);
            if (r1 < N_NODES)
                *reinterpret_cast<float2*>(g_h + (size_t)r1 * H_DIM + col) =
                    make_float2(acc[mt][nt][2], acc[mt][nt][3]);
        }
    }
#undef LOAD_GLOBAL
#undef STORE_SMEM
}

// ---------------------------------------------------------------------------
// layer-1 aggregation
// ---------------------------------------------------------------------------
__global__ void k_agg1_init() {   // self-loop term, full overwrite
    int idx = blockIdx.x * blockDim.x + threadIdx.x;   // N*32 float4 slots
    if (idx >= N_NODES * 32) return;
    int n = idx >> 5;
    float s = g_dinv[n]; s = s * s;
    float4 v = *reinterpret_cast<const float4*>(g_h + (size_t)idx * 4);
    v.x *= s; v.y *= s; v.z *= s; v.w *= s;
    *reinterpret_cast<float4*>(g_agg + (size_t)idx * 4) = v;
}

__global__ void k_scatter1(const int* __restrict__ edges, int E) {
    int idx = blockIdx.x * blockDim.x + threadIdx.x;   // E*32 (edge, col4)
    if (idx >= E * 32) return;
    int e = idx >> 5;
    int g = idx & 31;
    int s = edges[e];
    int d = edges[E + e];
    float norm = g_dinv[s] * g_dinv[d];
    float4 v = *reinterpret_cast<const float4*>(g_h + (size_t)s * H_DIM + g * 4);
    float* p = g_agg + (size_t)d * H_DIM + g * 4;
    asm volatile("red.global.add.v4.f32 [%0], {%1,%2,%3,%4};"
                 :: "l"(p), "f"(v.x * norm), "f"(v.y * norm),
                    "f"(v.z * norm), "f"(v.w * norm)
                 : "memory");
}

__global__ void k_bias_relu(const float* __restrict__ b1) {
    int idx = blockIdx.x * blockDim.x + threadIdx.x;   // N*32 float4 slots
    if (idx >= N_NODES * 32) return;
    int j4 = (idx & 31) * 4;
    float4 b = *reinterpret_cast<const float4*>(b1 + j4);
    float4 v = *reinterpret_cast<const float4*>(g_agg + (size_t)idx * 4);
    v.x = fmaxf(v.x + b.x, 0.f);
    v.y = fmaxf(v.y + b.y, 0.f);
    v.z = fmaxf(v.z + b.z, 0.f);
    v.w = fmaxf(v.w + b.w, 0.f);
    *reinterpret_cast<float4*>(g_h + (size_t)idx * 4) = v;
}

// ---------------------------------------------------------------------------
// GEMM2: z = h1 @ W2   [20000 x 128] @ [128 x 70] — warp per row
// ---------------------------------------------------------------------------
__global__ __launch_bounds__(256) void k_gemm2(const float* __restrict__ W2) {
    __shared__ float W2s[H_DIM * C_DIM];   // 35840 B
    int tid = threadIdx.x;
    for (int i = tid; i < H_DIM * C_DIM; i += 256) W2s[i] = W2[i];
    __syncthreads();

    int warp = tid >> 5, lane = tid & 31;
    int n = blockIdx.x * 8 + warp;
    if (n >= N_NODES) return;
    const float* hr = g_h + (size_t)n * H_DIM;

    float a0 = 0.f, a1 = 0.f, a2 = 0.f;
#pragma unroll 4
    for (int k = 0; k < H_DIM; k++) {
        float hv = __ldg(hr + k);                  // uniform per warp
        const float* wr = W2s + k * C_DIM;
        a0 += hv * wr[lane];
        a1 += hv * wr[lane + 32];
        if (lane < C_DIM - 64) a2 += hv * wr[lane + 64];
    }
    float* zr = g_z + (size_t)n * C_DIM;
    zr[lane]      = a0;
    zr[lane + 32] = a1;
    if (lane < C_DIM - 64) zr[lane + 64] = a2;
}

// ---------------------------------------------------------------------------
// layer-2 aggregation (into d_out) + softmax
// ---------------------------------------------------------------------------
__global__ void k_agg2_init(float* __restrict__ out) {
    int idx = blockIdx.x * blockDim.x + threadIdx.x;   // N*70
    if (idx >= N_NODES * C_DIM) return;
    int n = idx / C_DIM;
    float s = g_dinv[n]; s = s * s;
    out[idx] = g_z[idx] * s;
}

__global__ void k_scatter2(const int* __restrict__ edges, int E,
                           float* __restrict__ out) {
    int idx = blockIdx.x * blockDim.x + threadIdx.x;   // E*70
    if (idx >= E * C_DIM) return;
    int e = idx / C_DIM;
    int c = idx - e * C_DIM;
    int s = edges[e];
    int d = edges[E + e];
    float norm = g_dinv[s] * g_dinv[d];
    atomicAdd(&out[(size_t)d * C_DIM + c], g_z[(size_t)s * C_DIM + c] * norm);
}

__global__ __launch_bounds__(256) void k_softmax(const float* __restrict__ b2,
                                                 float* __restrict__ out) {
    int warp = threadIdx.x >> 5, lane = threadIdx.x & 31;
    int n = blockIdx.x * 8 + warp;
    if (n >= N_NODES) return;
    float* r = out + (size_t)n * C_DIM;

    float v0 = r[lane] + b2[lane];
    float v1 = r[lane + 32] + b2[lane + 32];
    float v2 = (lane < C_DIM - 64) ? r[lane + 64] + b2[lane + 64] : -INFINITY;

    float m = fmaxf(fmaxf(v0, v1), v2);
#pragma unroll
    for (int o = 16; o > 0; o >>= 1) m = fmaxf(m, __shfl_xor_sync(0xffffffff, m, o));

    float e0 = expf(v0 - m);
    float e1 = expf(v1 - m);
    float e2 = (lane < C_DIM - 64) ? expf(v2 - m) : 0.f;
    float s = e0 + e1 + e2;
#pragma unroll
    for (int o = 16; o > 0; o >>= 1) s += __shfl_xor_sync(0xffffffff, s, o);
    float inv = 1.f / s;

    r[lane]      = e0 * inv;
    r[lane + 32] = e1 * inv;
    if (lane < C_DIM - 64) r[lane + 64] = e2 * inv;
}

// ---------------------------------------------------------------------------
extern "C" void kernel_launch(void* const* d_in, const int* in_sizes, int n_in,
                              void* d_out, int out_size) {
    const float* x  = (const float*)d_in[0];
    const int* edges = (const int*)d_in[1];
    const float* W1 = (const float*)d_in[2];
    const float* b1 = (const float*)d_in[3];
    const float* W2 = (const float*)d_in[4];
    const float* b2 = (const float*)d_in[5];
    float* out = (float*)d_out;
    const int E = in_sizes[1] / 2;

    // degree / dinv
    k_zero_deg<<<(N_NODES + 255) / 256, 256>>>();
    k_count_deg<<<(E + 255) / 256, 256>>>(edges, E);
    k_dinv<<<(N_NODES + 255) / 256, 256>>>();

    // layer 1
    k_gemm1_tc<<<(N_NODES + 63) / 64, 128>>>(x, W1);
    k_agg1_init<<<(N_NODES * 32 + 255) / 256, 256>>>();
    k_scatter1<<<(E * 32 + 255) / 256, 256>>>(edges, E);
    k_bias_relu<<<(N_NODES * 32 + 255) / 256, 256>>>(b1);

    // layer 2
    k_gemm2<<<(N_NODES + 7) / 8, 256>>>(W2);
    k_agg2_init<<<(N_NODES * C_DIM + 255) / 256, 256>>>(out);
    k_scatter2<<<(E * C_DIM + 255) / 256, 256>>>(edges, E, out);
    k_softmax<<<(N_NODES + 7) / 8, 256>>>(b2, out);
}

// round 3
// speedup vs baseline: 2.8688x; 1.1536x over previous
#include <cuda_runtime.h>
#include <math.h>

#define N_NODES 20000
#define K_IN    8710
#define H_DIM   128
#define C_DIM   70

// ---- scratch (static device globals; no allocation allowed) ----
__device__ float g_h[(size_t)N_NODES * H_DIM];    // x@W1, then relu(agg+b1)
__device__ float g_agg[(size_t)N_NODES * H_DIM];  // layer-1 aggregation
__device__ float g_z[(size_t)N_NODES * C_DIM];    // h1@W2
__device__ int   g_deg[N_NODES];
__device__ float g_dinv[N_NODES];

// ---------------------------------------------------------------------------
// degree / normalization
// ---------------------------------------------------------------------------
__global__ void k_zero_deg() {
    int i = blockIdx.x * blockDim.x + threadIdx.x;
    if (i < N_NODES) g_deg[i] = 0;
}

__global__ void k_count_deg(const int* __restrict__ edges, int E) {
    int e = blockIdx.x * blockDim.x + threadIdx.x;
    if (e < E) atomicAdd(&g_deg[edges[E + e]], 1);   // dst
}

__global__ void k_dinv() {
    int i = blockIdx.x * blockDim.x + threadIdx.x;
    if (i < N_NODES) g_dinv[i] = rsqrtf((float)(g_deg[i] + 1));  // +1 self loop
}

// ---------------------------------------------------------------------------
// GEMM1, tf32 HMMA + cp.async 4-stage pipeline
// h = x @ W1  [20000 x 8710] @ [8710 x 128]
// BM=128, BN=128, BK=16, 256 threads = 8 warps (4m x 2n), warp tile 32x64
// ---------------------------------------------------------------------------
#define NC_CHUNKS ((K_IN + 15) / 16)   // 545
#define G1_STAGES 4
#define G1_BM 128
#define G1_BK 16
#define A_STRIDE 20                      // pad: 32 distinct banks across a warp
#define B_STRIDE 136                     // pad: 32 distinct banks across a warp
#define A_WORDS (G1_BM * A_STRIDE)       // 2560
#define STAGE_WORDS (A_WORDS + G1_BK * B_STRIDE)   // 2560 + 2176 = 4736
#define G1_SMEM_BYTES (G1_STAGES * STAGE_WORDS * 4)  // 75776

__device__ __forceinline__ unsigned f2tf(float f) {
    unsigned u;
    asm("cvt.rna.tf32.f32 %0, %1;" : "=r"(u) : "f"(f));
    return u;
}

__device__ __forceinline__ unsigned smem_u32(const void* p) {
    unsigned a;
    asm("{ .reg .u64 t; cvta.to.shared.u64 t, %1; cvt.u32.u64 %0, t; }"
        : "=r"(a) : "l"(p));
    return a;
}

__global__ __launch_bounds__(256, 2) void k_gemm1_tc(const float* __restrict__ X,
                                                     const float* __restrict__ W) {
    extern __shared__ float sm[];

    const int tid  = threadIdx.x;
    const int warp = tid >> 5;
    const int lane = tid & 31;
    const int gid  = lane >> 2;     // 0..7
    const int tig  = lane & 3;      // 0..3
    const int warp_m = warp >> 1;   // 0..3
    const int warp_n = warp & 1;    // 0..1
    const int m0 = blockIdx.x * G1_BM;
    const unsigned sm_base = smem_u32(sm);

    float acc[2][8][4];
#pragma unroll
    for (int i = 0; i < 2; i++)
#pragma unroll
        for (int j = 0; j < 8; j++)
#pragma unroll
            for (int t = 0; t < 4; t++) acc[i][j][t] = 0.f;

    // stage loader: chunk c -> stage c % G1_STAGES; always commits a group
#define LOAD_STAGE(c)                                                             \
    {                                                                             \
        const int stg = (c) % G1_STAGES;                                          \
        const unsigned a_u = sm_base + stg * (STAGE_WORDS * 4);                   \
        const unsigned b_u = a_u + A_WORDS * 4;                                   \
        const int k0 = (c) * G1_BK;                                               \
        const bool inr = (c) < NC_CHUNKS;                                         \
        _Pragma("unroll")                                                         \
        for (int i = 0; i < 4; i++) {                                             \
            int p = tid + i * 256;                                                \
            int row = p >> 3;                                                     \
            int kp  = (p & 7) * 2;                                                \
            int gm = m0 + row, gk = k0 + kp;                                      \
            int ok = (inr && gm < N_NODES && gk + 1 < K_IN) ? 8 : 0;              \
            int gmc = gm < N_NODES ? gm : N_NODES - 1;                            \
            int gkc = gk + 1 < K_IN ? gk : 0;                                     \
            const float* src = X + (size_t)gmc * K_IN + gkc;                      \
            unsigned dst = a_u + (row * A_STRIDE + kp) * 4;                       \
            asm volatile("cp.async.ca.shared.global [%0], [%1], 8, %2;"           \
                         :: "r"(dst), "l"(src), "r"(ok));                         \
        }                                                                         \
        _Pragma("unroll")                                                         \
        for (int i = 0; i < 2; i++) {                                             \
            int q = tid + i * 256;                                                \
            int kr = q >> 5;                                                      \
            int nc = (q & 31) * 4;                                                \
            int gk = k0 + kr;                                                     \
            int ok = (inr && gk < K_IN) ? 16 : 0;                                 \
            int gkc = gk < K_IN ? gk : 0;                                         \
            const float* src = W + (size_t)gkc * H_DIM + nc;                      \
            unsigned dst = b_u + (kr * B_STRIDE + nc) * 4;                        \
            asm volatile("cp.async.cg.shared.global [%0], [%1], 16, %2;"          \
                         :: "r"(dst), "l"(src), "r"(ok));                         \
        }                                                                         \
        asm volatile("cp.async.commit_group;");                                   \
    }

    // prologue: stages 0..2
    LOAD_STAGE(0);
    LOAD_STAGE(1);
    LOAD_STAGE(2);

    for (int c = 0; c < NC_CHUNKS; ++c) {
        asm volatile("cp.async.wait_group %0;" :: "n"(G1_STAGES - 2));
        __syncthreads();

        // refill the stage consumed last iteration
        LOAD_STAGE(c + G1_STAGES - 1);

        const float* As = sm + (c % G1_STAGES) * STAGE_WORDS;
        const float* Bs = As + A_WORDS;

#pragma unroll
        for (int ks = 0; ks < 2; ks++) {
            const int kb = ks * 8;
            unsigned af[2][4];
#pragma unroll
            for (int mt = 0; mt < 2; mt++) {
                int r = warp_m * 32 + mt * 16 + gid;
                af[mt][0] = f2tf(As[r * A_STRIDE + kb + tig]);
                af[mt][1] = f2tf(As[(r + 8) * A_STRIDE + kb + tig]);
                af[mt][2] = f2tf(As[r * A_STRIDE + kb + tig + 4]);
                af[mt][3] = f2tf(As[(r + 8) * A_STRIDE + kb + tig + 4]);
            }
            unsigned bf[8][2];
#pragma unroll
            for (int nt = 0; nt < 8; nt++) {
                int nb = warp_n * 64 + nt * 8 + gid;
                bf[nt][0] = f2tf(Bs[(kb + tig) * B_STRIDE + nb]);
                bf[nt][1] = f2tf(Bs[(kb + tig + 4) * B_STRIDE + nb]);
            }
#pragma unroll
            for (int mt = 0; mt < 2; mt++)
#pragma unroll
                for (int nt = 0; nt < 8; nt++) {
                    asm volatile(
                        "mma.sync.aligned.m16n8k8.row.col.f32.tf32.tf32.f32 "
                        "{%0,%1,%2,%3}, {%4,%5,%6,%7}, {%8,%9}, {%0,%1,%2,%3};"
                        : "+f"(acc[mt][nt][0]), "+f"(acc[mt][nt][1]),
                          "+f"(acc[mt][nt][2]), "+f"(acc[mt][nt][3])
                        : "r"(af[mt][0]), "r"(af[mt][1]), "r"(af[mt][2]), "r"(af[mt][3]),
                          "r"(bf[nt][0]), "r"(bf[nt][1]));
                }
        }
    }
#undef LOAD_STAGE

    // epilogue
#pragma unroll
    for (int mt = 0; mt < 2; mt++) {
        int r0 = m0 + warp_m * 32 + mt * 16 + gid;
        int r1 = r0 + 8;
#pragma unroll
        for (int nt = 0; nt < 8; nt++) {
            int col = warp_n * 64 + nt * 8 + tig * 2;
            if (r0 < N_NODES)
                *reinterpret_cast<float2*>(g_h + (size_t)r0 * H_DIM + col) =
                    make_float2(acc[mt][nt][0], acc[mt][nt][1]);
            if (r1 < N_NODES)
                *reinterpret_cast<float2*>(g_h + (size_t)r1 * H_DIM + col) =
                    make_float2(acc[mt][nt][2], acc[mt][nt][3]);
        }
    }
}

// ---------------------------------------------------------------------------
// layer-1 aggregation
// ---------------------------------------------------------------------------
__global__ void k_agg1_init() {   // self-loop term, full overwrite
    int idx = blockIdx.x * blockDim.x + threadIdx.x;   // N*32 float4 slots
    if (idx >= N_NODES * 32) return;
    int n = idx >> 5;
    float s = g_dinv[n]; s = s * s;
    float4 v = *reinterpret_cast<const float4*>(g_h + (size_t)idx * 4);
    v.x *= s; v.y *= s; v.z *= s; v.w *= s;
    *reinterpret_cast<float4*>(g_agg + (size_t)idx * 4) = v;
}

__global__ void k_scatter1(const int* __restrict__ edges, int E) {
    int idx = blockIdx.x * blockDim.x + threadIdx.x;   // E*32 (edge, col4)
    if (idx >= E * 32) return;
    int e = idx >> 5;
    int g = idx & 31;
    int s = edges[e];
    int d = edges[E + e];
    float norm = g_dinv[s] * g_dinv[d];
    float4 v = *reinterpret_cast<const float4*>(g_h + (size_t)s * H_DIM + g * 4);
    float* p = g_agg + (size_t)d * H_DIM + g * 4;
    asm volatile("red.global.add.v4.f32 [%0], {%1,%2,%3,%4};"
                 :: "l"(p), "f"(v.x * norm), "f"(v.y * norm),
                    "f"(v.z * norm), "f"(v.w * norm)
                 : "memory");
}

__global__ void k_bias_relu(const float* __restrict__ b1) {
    int idx = blockIdx.x * blockDim.x + threadIdx.x;   // N*32 float4 slots
    if (idx >= N_NODES * 32) return;
    int j4 = (idx & 31) * 4;
    float4 b = *reinterpret_cast<const float4*>(b1 + j4);
    float4 v = *reinterpret_cast<const float4*>(g_agg + (size_t)idx * 4);
    v.x = fmaxf(v.x + b.x, 0.f);
    v.y = fmaxf(v.y + b.y, 0.f);
    v.z = fmaxf(v.z + b.z, 0.f);
    v.w = fmaxf(v.w + b.w, 0.f);
    *reinterpret_cast<float4*>(g_h + (size_t)idx * 4) = v;
}

// ---------------------------------------------------------------------------
// GEMM2: z = h1 @ W2   [20000 x 128] @ [128 x 70] — warp per row
// ---------------------------------------------------------------------------
__global__ __launch_bounds__(256) void k_gemm2(const float* __restrict__ W2) {
    __shared__ float W2s[H_DIM * C_DIM];   // 35840 B
    int tid = threadIdx.x;
    for (int i = tid; i < H_DIM * C_DIM; i += 256) W2s[i] = W2[i];
    __syncthreads();

    int warp = tid >> 5, lane = tid & 31;
    int n = blockIdx.x * 8 + warp;
    if (n >= N_NODES) return;
    const float* hr = g_h + (size_t)n * H_DIM;

    float a0 = 0.f, a1 = 0.f, a2 = 0.f;
#pragma unroll 4
    for (int k = 0; k < H_DIM; k++) {
        float hv = __ldg(hr + k);                  // uniform per warp
        const float* wr = W2s + k * C_DIM;
        a0 += hv * wr[lane];
        a1 += hv * wr[lane + 32];
        if (lane < C_DIM - 64) a2 += hv * wr[lane + 64];
    }
    float* zr = g_z + (size_t)n * C_DIM;
    zr[lane]      = a0;
    zr[lane + 32] = a1;
    if (lane < C_DIM - 64) zr[lane + 64] = a2;
}

// ---------------------------------------------------------------------------
// layer-2 aggregation (into d_out) + softmax
// ---------------------------------------------------------------------------
__global__ void k_agg2_init(float* __restrict__ out) {
    int idx = blockIdx.x * blockDim.x + threadIdx.x;   // N*70
    if (idx >= N_NODES * C_DIM) return;
    int n = idx / C_DIM;
    float s = g_dinv[n]; s = s * s;
    out[idx] = g_z[idx] * s;
}

__global__ void k_scatter2(const int* __restrict__ edges, int E,
                           float* __restrict__ out) {
    int idx = blockIdx.x * blockDim.x + threadIdx.x;   // E*32: warp per edge
    if (idx >= E * 32) return;
    int e = idx >> 5;
    int lane = idx & 31;
    int s = edges[e];
    int d = edges[E + e];
    float norm = g_dinv[s] * g_dinv[d];
    const float* zr = g_z + (size_t)s * C_DIM;
    float* orow = out + (size_t)d * C_DIM;

    {   // c pairs 0..31 -> cols 0..63
        float2 v = *reinterpret_cast<const float2*>(zr + 2 * lane);
        asm volatile("red.global.add.v2.f32 [%0], {%1,%2};"
                     :: "l"(orow + 2 * lane), "f"(v.x * norm), "f"(v.y * norm)
                     : "memory");
    }
    if (lane < 3) {   // pairs 32..34 -> cols 64..69
        float2 v = *reinterpret_cast<const float2*>(zr + 64 + 2 * lane);
        asm volatile("red.global.add.v2.f32 [%0], {%1,%2};"
                     :: "l"(orow + 64 + 2 * lane), "f"(v.x * norm), "f"(v.y * norm)
                     : "memory");
    }
}

__global__ __launch_bounds__(256) void k_softmax(const float* __restrict__ b2,
                                                 float* __restrict__ out) {
    int warp = threadIdx.x >> 5, lane = threadIdx.x & 31;
    int n = blockIdx.x * 8 + warp;
    if (n >= N_NODES) return;
    float* r = out + (size_t)n * C_DIM;

    float v0 = r[lane] + b2[lane];
    float v1 = r[lane + 32] + b2[lane + 32];
    float v2 = (lane < C_DIM - 64) ? r[lane + 64] + b2[lane + 64] : -INFINITY;

    float m = fmaxf(fmaxf(v0, v1), v2);
#pragma unroll
    for (int o = 16; o > 0; o >>= 1) m = fmaxf(m, __shfl_xor_sync(0xffffffff, m, o));

    float e0 = expf(v0 - m);
    float e1 = expf(v1 - m);
    float e2 = (lane < C_DIM - 64) ? expf(v2 - m) : 0.f;
    float s = e0 + e1 + e2;
#pragma unroll
    for (int o = 16; o > 0; o >>= 1) s += __shfl_xor_sync(0xffffffff, s, o);
    float inv = 1.f / s;

    r[lane]      = e0 * inv;
    r[lane + 32] = e1 * inv;
    if (lane < C_DIM - 64) r[lane + 64] = e2 * inv;
}

// ---------------------------------------------------------------------------
extern "C" void kernel_launch(void* const* d_in, const int* in_sizes, int n_in,
                              void* d_out, int out_size) {
    const float* x  = (const float*)d_in[0];
    const int* edges = (const int*)d_in[1];
    const float* W1 = (const float*)d_in[2];
    const float* b1 = (const float*)d_in[3];
    const float* W2 = (const float*)d_in[4];
    const float* b2 = (const float*)d_in[5];
    float* out = (float*)d_out;
    const int E = in_sizes[1] / 2;

    // opt-in to >48KB dynamic smem (idempotent; not a stream op)
    cudaFuncSetAttribute(k_gemm1_tc, cudaFuncAttributeMaxDynamicSharedMemorySize,
                         G1_SMEM_BYTES);

    // degree / dinv
    k_zero_deg<<<(N_NODES + 255) / 256, 256>>>();
    k_count_deg<<<(E + 255) / 256, 256>>>(edges, E);
    k_dinv<<<(N_NODES + 255) / 256, 256>>>();

    // layer 1
    k_gemm1_tc<<<(N_NODES + G1_BM - 1) / G1_BM, 256, G1_SMEM_BYTES>>>(x, W1);
    k_agg1_init<<<(N_NODES * 32 + 255) / 256, 256>>>();
    k_scatter1<<<(E * 32 + 255) / 256, 256>>>(edges, E);
    k_bias_relu<<<(N_NODES * 32 + 255) / 256, 256>>>(b1);

    // layer 2
    k_gemm2<<<(N_NODES + 7) / 8, 256>>>(W2);
    k_agg2_init<<<(N_NODES * C_DIM + 255) / 256, 256>>>(out);
    k_scatter2<<<(E * 32 + 255) / 256, 256>>>(edges, E, out);
    k_softmax<<<(N_NODES + 7) / 8, 256>>>(b2, out);
}

// round 6
// speedup vs baseline: 3.0195x; 1.0526x over previous
#include <cuda_runtime.h>
#include <math.h>
#include <stdint.h>

#define N_NODES 20000
#define K_IN    8710
#define H_DIM   128
#define C_DIM   70

// ---- scratch (static device globals; no allocation allowed) ----
__device__ float g_h[(size_t)N_NODES * H_DIM];    // x@W1, then relu(agg+b1)
__device__ float g_agg[(size_t)N_NODES * H_DIM];  // layer-1 aggregation
__device__ float g_z[(size_t)N_NODES * C_DIM];    // h1@W2
__device__ float g_Wr[(size_t)K_IN * H_DIM];      // W1 pre-rounded to tf32
__device__ int   g_deg[N_NODES];
__device__ float g_dinv[N_NODES];

// ---------------------------------------------------------------------------
// degree / normalization
// ---------------------------------------------------------------------------
__global__ void k_zero_deg() {
    int i = blockIdx.x * blockDim.x + threadIdx.x;
    if (i < N_NODES) g_deg[i] = 0;
}

__global__ void k_count_deg(const int* __restrict__ edges, int E) {
    int e = blockIdx.x * blockDim.x + threadIdx.x;
    if (e < E) atomicAdd(&g_deg[edges[E + e]], 1);   // dst
}

__global__ void k_dinv() {
    int i = blockIdx.x * blockDim.x + threadIdx.x;
    if (i < N_NODES) g_dinv[i] = rsqrtf((float)(g_deg[i] + 1));  // +1 self loop
}

// ---------------------------------------------------------------------------
// pre-round W1 to tf32 (rna) so GEMM needs no in-loop cvt for B
// ---------------------------------------------------------------------------
__global__ void k_round_w(const float* __restrict__ W1) {
    int i = blockIdx.x * blockDim.x + threadIdx.x;
    if (i < K_IN * H_DIM) {
        unsigned u;
        asm("cvt.rna.tf32.f32 %0, %1;" : "=r"(u) : "f"(W1[i]));
        g_Wr[i] = __uint_as_float(u);
    }
}

// ---------------------------------------------------------------------------
// GEMM1, tf32 HMMA + cp.async 4-stage pipeline, NO in-loop cvt
// h = x @ W1  [20000 x 8710] @ [8710 x 128]
// BM=128, BN=128, BK=16, 256 threads = 8 warps (4m x 2n), warp tile 32x64
// A fed as raw fp32 bits (HW truncates to tf32); compensated in epilogue.
// ---------------------------------------------------------------------------
#define NC_CHUNKS ((K_IN + 15) / 16)   // 545
#define G1_STAGES 4
#define G1_BM 128
#define G1_BK 16
#define A_STRIDE 20
#define B_STRIDE 136
#define A_WORDS (G1_BM * A_STRIDE)                   // 2560
#define STAGE_WORDS (A_WORDS + G1_BK * B_STRIDE)     // 4736
#define G1_SMEM_BYTES (G1_STAGES * STAGE_WORDS * 4)  // 75776
#define TRUNC_COMP 1.00034f   // E[tf32-truncation shrink] of A ≈ 2^-11 * ln2 compensation

__device__ __forceinline__ unsigned smem_u32(const void* p) {
    unsigned a;
    asm("{ .reg .u64 t; cvta.to.shared.u64 t, %1; cvt.u32.u64 %0, t; }"
        : "=r"(a) : "l"(p));
    return a;
}

__global__ __launch_bounds__(256, 2) void k_gemm1_tc(const float* __restrict__ X) {
    extern __shared__ float sm[];

    const int tid  = threadIdx.x;
    const int warp = tid >> 5;
    const int lane = tid & 31;
    const int gid  = lane >> 2;     // 0..7
    const int tig  = lane & 3;      // 0..3
    const int warp_m = warp >> 1;   // 0..3
    const int warp_n = warp & 1;    // 0..1
    const int m0 = blockIdx.x * G1_BM;
    const unsigned sm_base = smem_u32(sm);

    float acc[2][8][4];
#pragma unroll
    for (int i = 0; i < 2; i++)
#pragma unroll
        for (int j = 0; j < 8; j++)
#pragma unroll
            for (int t = 0; t < 4; t++) acc[i][j][t] = 0.f;

#define LOAD_STAGE(c)                                                             \
    {                                                                             \
        const int stg = (c) % G1_STAGES;                                          \
        const unsigned a_u = sm_base + stg * (STAGE_WORDS * 4);                   \
        const unsigned b_u = a_u + A_WORDS * 4;                                   \
        const int k0 = (c) * G1_BK;                                               \
        const bool inr = (c) < NC_CHUNKS;                                         \
        _Pragma("unroll")                                                         \
        for (int i = 0; i < 4; i++) {                                             \
            int p = tid + i * 256;                                                \
            int row = p >> 3;                                                     \
            int kp  = (p & 7) * 2;                                                \
            int gm = m0 + row, gk = k0 + kp;                                      \
            int ok = (inr && gm < N_NODES && gk + 1 < K_IN) ? 8 : 0;              \
            int gmc = gm < N_NODES ? gm : N_NODES - 1;                            \
            int gkc = gk + 1 < K_IN ? gk : 0;                                     \
            const float* src = X + (size_t)gmc * K_IN + gkc;                      \
            unsigned dst = a_u + (row * A_STRIDE + kp) * 4;                       \
            asm volatile("cp.async.ca.shared.global [%0], [%1], 8, %2;"           \
                         :: "r"(dst), "l"(src), "r"(ok));                         \
        }                                                                         \
        _Pragma("unroll")                                                         \
        for (int i = 0; i < 2; i++) {                                             \
            int q = tid + i * 256;                                                \
            int kr = q >> 5;                                                      \
            int nc = (q & 31) * 4;                                                \
            int gk = k0 + kr;                                                     \
            int ok = (inr && gk < K_IN) ? 16 : 0;                                 \
            int gkc = gk < K_IN ? gk : 0;                                         \
            const float* src = g_Wr + (size_t)gkc * H_DIM + nc;                   \
            unsigned dst = b_u + (kr * B_STRIDE + nc) * 4;                        \
            asm volatile("cp.async.cg.shared.global [%0], [%1], 16, %2;"          \
                         :: "r"(dst), "l"(src), "r"(ok));                         \
        }                                                                         \
        asm volatile("cp.async.commit_group;");                                   \
    }

    LOAD_STAGE(0);
    LOAD_STAGE(1);
    LOAD_STAGE(2);

    for (int c = 0; c < NC_CHUNKS; ++c) {
        asm volatile("cp.async.wait_group %0;" :: "n"(G1_STAGES - 2));
        __syncthreads();

        LOAD_STAGE(c + G1_STAGES - 1);

        const unsigned* As = reinterpret_cast<const unsigned*>(
            sm + (c % G1_STAGES) * STAGE_WORDS);
        const unsigned* Bs = As + A_WORDS;

#pragma unroll
        for (int ks = 0; ks < 2; ks++) {
            const int kb = ks * 8;
            unsigned af[2][4];
#pragma unroll
            for (int mt = 0; mt < 2; mt++) {
                int r = warp_m * 32 + mt * 16 + gid;
                af[mt][0] = As[r * A_STRIDE + kb + tig];
                af[mt][1] = As[(r + 8) * A_STRIDE + kb + tig];
                af[mt][2] = As[r * A_STRIDE + kb + tig + 4];
                af[mt][3] = As[(r + 8) * A_STRIDE + kb + tig + 4];
            }
            unsigned bf[8][2];
#pragma unroll
            for (int nt = 0; nt < 8; nt++) {
                int nb = warp_n * 64 + nt * 8 + gid;
                bf[nt][0] = Bs[(kb + tig) * B_STRIDE + nb];
                bf[nt][1] = Bs[(kb + tig + 4) * B_STRIDE + nb];
            }
#pragma unroll
            for (int mt = 0; mt < 2; mt++)
#pragma unroll
                for (int nt = 0; nt < 8; nt++) {
                    asm volatile(
                        "mma.sync.aligned.m16n8k8.row.col.f32.tf32.tf32.f32 "
                        "{%0,%1,%2,%3}, {%4,%5,%6,%7}, {%8,%9}, {%0,%1,%2,%3};"
                        : "+f"(acc[mt][nt][0]), "+f"(acc[mt][nt][1]),
                          "+f"(acc[mt][nt][2]), "+f"(acc[mt][nt][3])
                        : "r"(af[mt][0]), "r"(af[mt][1]), "r"(af[mt][2]), "r"(af[mt][3]),
                          "r"(bf[nt][0]), "r"(bf[nt][1]));
                }
        }
    }
#undef LOAD_STAGE

    // epilogue: truncation compensation + fused agg-init (g_agg = h * dinv^2)
#pragma unroll
    for (int mt = 0; mt < 2; mt++) {
        int r0 = m0 + warp_m * 32 + mt * 16 + gid;
        int r1 = r0 + 8;
        float s0 = 0.f, s1 = 0.f;
        if (r0 < N_NODES) { float dv = g_dinv[r0]; s0 = dv * dv; }
        if (r1 < N_NODES) { float dv = g_dinv[r1]; s1 = dv * dv; }
#pragma unroll
        for (int nt = 0; nt < 8; nt++) {
            int col = warp_n * 64 + nt * 8 + tig * 2;
            if (r0 < N_NODES) {
                float h0 = acc[mt][nt][0] * TRUNC_COMP;
                float h1 = acc[mt][nt][1] * TRUNC_COMP;
                *reinterpret_cast<float2*>(g_h + (size_t)r0 * H_DIM + col) =
                    make_float2(h0, h1);
                *reinterpret_cast<float2*>(g_agg + (size_t)r0 * H_DIM + col) =
                    make_float2(h0 * s0, h1 * s0);
            }
            if (r1 < N_NODES) {
                float h2 = acc[mt][nt][2] * TRUNC_COMP;
                float h3 = acc[mt][nt][3] * TRUNC_COMP;
                *reinterpret_cast<float2*>(g_h + (size_t)r1 * H_DIM + col) =
                    make_float2(h2, h3);
                *reinterpret_cast<float2*>(g_agg + (size_t)r1 * H_DIM + col) =
                    make_float2(h2 * s1, h3 * s1);
            }
        }
    }
}

// ---------------------------------------------------------------------------
// layer-1 aggregation (agg init fused into gemm1 epilogue)
// ---------------------------------------------------------------------------
__global__ void k_scatter1(const int* __restrict__ edges, int E) {
    int idx = blockIdx.x * blockDim.x + threadIdx.x;   // E*32 (edge, col4)
    if (idx >= E * 32) return;
    int e = idx >> 5;
    int g = idx & 31;
    int s = edges[e];
    int d = edges[E + e];
    float norm = g_dinv[s] * g_dinv[d];
    float4 v = *reinterpret_cast<const float4*>(g_h + (size_t)s * H_DIM + g * 4);
    float* p = g_agg + (size_t)d * H_DIM + g * 4;
    asm volatile("red.global.add.v4.f32 [%0], {%1,%2,%3,%4};"
                 :: "l"(p), "f"(v.x * norm), "f"(v.y * norm),
                    "f"(v.z * norm), "f"(v.w * norm)
                 : "memory");
}

__global__ void k_bias_relu(const float* __restrict__ b1) {
    int idx = blockIdx.x * blockDim.x + threadIdx.x;   // N*32 float4 slots
    if (idx >= N_NODES * 32) return;
    int j4 = (idx & 31) * 4;
    float4 b = *reinterpret_cast<const float4*>(b1 + j4);
    float4 v = *reinterpret_cast<const float4*>(g_agg + (size_t)idx * 4);
    v.x = fmaxf(v.x + b.x, 0.f);
    v.y = fmaxf(v.y + b.y, 0.f);
    v.z = fmaxf(v.z + b.z, 0.f);
    v.w = fmaxf(v.w + b.w, 0.f);
    *reinterpret_cast<float4*>(g_h + (size_t)idx * 4) = v;
}

// ---------------------------------------------------------------------------
// GEMM2: z = h1 @ W2   [20000 x 128] @ [128 x 70] — warp per row
// ---------------------------------------------------------------------------
__global__ __launch_bounds__(256) void k_gemm2(const float* __restrict__ W2) {
    __shared__ float W2s[H_DIM * C_DIM];   // 35840 B
    int tid = threadIdx.x;
    for (int i = tid; i < H_DIM * C_DIM; i += 256) W2s[i] = W2[i];
    __syncthreads();

    int warp = tid >> 5, lane = tid & 31;
    int n = blockIdx.x * 8 + warp;
    if (n >= N_NODES) return;
    const float* hr = g_h + (size_t)n * H_DIM;

    float a0 = 0.f, a1 = 0.f, a2 = 0.f;
#pragma unroll 4
    for (int k = 0; k < H_DIM; k++) {
        float hv = __ldg(hr + k);                  // uniform per warp
        const float* wr = W2s + k * C_DIM;
        a0 += hv * wr[lane];
        a1 += hv * wr[lane + 32];
        if (lane < C_DIM - 64) a2 += hv * wr[lane + 64];
    }
    float* zr = g_z + (size_t)n * C_DIM;
    zr[lane]      = a0;
    zr[lane + 32] = a1;
    if (lane < C_DIM - 64) zr[lane + 64] = a2;
}

// ---------------------------------------------------------------------------
// layer-2 aggregation (into d_out) + softmax
// ---------------------------------------------------------------------------
__global__ void k_agg2_init(float* __restrict__ out) {
    int idx = blockIdx.x * blockDim.x + threadIdx.x;   // N*70
    if (idx >= N_NODES * C_DIM) return;
    int n = idx / C_DIM;
    float s = g_dinv[n]; s = s * s;
    out[idx] = g_z[idx] * s;
}

__global__ void k_scatter2(const int* __restrict__ edges, int E,
                           float* __restrict__ out) {
    int idx = blockIdx.x * blockDim.x + threadIdx.x;   // E*32: warp per edge
    if (idx >= E * 32) return;
    int e = idx >> 5;
    int lane = idx & 31;
    int s = edges[e];
    int d = edges[E + e];
    float norm = g_dinv[s] * g_dinv[d];
    const float* zr = g_z + (size_t)s * C_DIM;
    float* orow = out + (size_t)d * C_DIM;

    {   // pairs 0..31 -> cols 0..63
        float2 v = *reinterpret_cast<const float2*>(zr + 2 * lane);
        asm volatile("red.global.add.v2.f32 [%0], {%1,%2};"
                     :: "l"(orow + 2 * lane), "f"(v.x * norm), "f"(v.y * norm)
                     : "memory");
    }
    if (lane < 3) {   // pairs 32..34 -> cols 64..69
        float2 v = *reinterpret_cast<const float2*>(zr + 64 + 2 * lane);
        asm volatile("red.global.add.v2.f32 [%0], {%1,%2};"
                     :: "l"(orow + 64 + 2 * lane), "f"(v.x * norm), "f"(v.y * norm)
                     : "memory");
    }
}

__global__ __launch_bounds__(256) void k_softmax(const float* __restrict__ b2,
                                                 float* __restrict__ out) {
    int warp = threadIdx.x >> 5, lane = threadIdx.x & 31;
    int n = blockIdx.x * 8 + warp;
    if (n >= N_NODES) return;
    float* r = out + (size_t)n * C_DIM;

    float v0 = r[lane] + b2[lane];
    float v1 = r[lane + 32] + b2[lane + 32];
    float v2 = (lane < C_DIM - 64) ? r[lane + 64] + b2[lane + 64] : -INFINITY;

    float m = fmaxf(fmaxf(v0, v1), v2);
#pragma unroll
    for (int o = 16; o > 0; o >>= 1) m = fmaxf(m, __shfl_xor_sync(0xffffffff, m, o));

    float e0 = expf(v0 - m);
    float e1 = expf(v1 - m);
    float e2 = (lane < C_DIM - 64) ? expf(v2 - m) : 0.f;
    float s = e0 + e1 + e2;
#pragma unroll
    for (int o = 16; o > 0; o >>= 1) s += __shfl_xor_sync(0xffffffff, s, o);
    float inv = 1.f / s;

    r[lane]      = e0 * inv;
    r[lane + 32] = e1 * inv;
    if (lane < C_DIM - 64) r[lane + 64] = e2 * inv;
}

// ---------------------------------------------------------------------------
extern "C" void kernel_launch(void* const* d_in, const int* in_sizes, int n_in,
                              void* d_out, int out_size) {
    const float* x  = (const float*)d_in[0];
    const int* edges = (const int*)d_in[1];
    const float* W1 = (const float*)d_in[2];
    const float* b1 = (const float*)d_in[3];
    const float* W2 = (const float*)d_in[4];
    const float* b2 = (const float*)d_in[5];
    float* out = (float*)d_out;
    const int E = in_sizes[1] / 2;

    cudaFuncSetAttribute(k_gemm1_tc, cudaFuncAttributeMaxDynamicSharedMemorySize,
                         G1_SMEM_BYTES);

    // degree / dinv + weight pre-rounding
    k_zero_deg<<<(N_NODES + 255) / 256, 256>>>();
    k_count_deg<<<(E + 255) / 256, 256>>>(edges, E);
    k_dinv<<<(N_NODES + 255) / 256, 256>>>();
    k_round_w<<<(K_IN * H_DIM + 255) / 256, 256>>>(W1);

    // layer 1 (epilogue writes g_h and g_agg = g_h * dinv^2)
    k_gemm1_tc<<<(N_NODES + G1_BM - 1) / G1_BM, 256, G1_SMEM_BYTES>>>(x);
    k_scatter1<<<(E * 32 + 255) / 256, 256>>>(edges, E);
    k_bias_relu<<<(N_NODES * 32 + 255) / 256, 256>>>(b1);

    // layer 2
    k_gemm2<<<(N_NODES + 7) / 8, 256>>>(W2);
    k_agg2_init<<<(N_NODES * C_DIM + 255) / 256, 256>>>(out);
    k_scatter2<<<(E * 32 + 255) / 256, 256>>>(edges, E, out);
    k_softmax<<<(N_NODES + 7) / 8, 256>>>(b2, out);
}

// round 8
// speedup vs baseline: 4.2084x; 1.3937x over previous
#include <cuda_runtime.h>
#include <math.h>
#include <stdint.h>

#define N_NODES 20000
#define K_IN    8710
#define H_DIM   128
#define C_DIM   70

// ---- scratch (static device globals; no allocation allowed) ----
__device__ float g_h[(size_t)N_NODES * H_DIM];    // x@W1, then relu(agg+b1)
__device__ float g_agg[(size_t)N_NODES * H_DIM];  // layer-1 aggregation
__device__ float g_z[(size_t)N_NODES * C_DIM];    // h1@W2
__device__ float g_Wr[(size_t)K_IN * H_DIM];      // W1 pre-rounded to tf32
__device__ int   g_deg[N_NODES];
__device__ float g_dinv[N_NODES];

// ---------------------------------------------------------------------------
// degree / normalization
// ---------------------------------------------------------------------------
__global__ void k_zero_deg() {
    int i = blockIdx.x * blockDim.x + threadIdx.x;
    if (i < N_NODES) g_deg[i] = 0;
}

__global__ void k_count_deg(const int* __restrict__ edges, int E) {
    int e = blockIdx.x * blockDim.x + threadIdx.x;
    if (e < E) atomicAdd(&g_deg[edges[E + e]], 1);   // dst
}

__global__ void k_dinv() {
    int i = blockIdx.x * blockDim.x + threadIdx.x;
    if (i < N_NODES) g_dinv[i] = rsqrtf((float)(g_deg[i] + 1));  // +1 self loop
}

// ---------------------------------------------------------------------------
// pre-round W1 to tf32 (rna) so GEMM needs no in-loop cvt for B
// ---------------------------------------------------------------------------
__global__ void k_round_w(const float* __restrict__ W1) {
    int i = blockIdx.x * blockDim.x + threadIdx.x;
    if (i < K_IN * H_DIM) {
        unsigned u;
        asm("cvt.rna.tf32.f32 %0, %1;" : "=r"(u) : "f"(W1[i]));
        g_Wr[i] = __uint_as_float(u);
    }
}

// ---------------------------------------------------------------------------
// zero-init g_h / g_agg rows of the split-K tiles (rows 18944..19999)
// ---------------------------------------------------------------------------
#define SPLIT_ROW0 18944
__global__ void k_zero_tail() {
    int idx = blockIdx.x * blockDim.x + threadIdx.x;   // float4 slots
    int total = (N_NODES - SPLIT_ROW0) * 32;           // 1056 * 32
    if (idx >= total) return;
    float4 z = make_float4(0.f, 0.f, 0.f, 0.f);
    *reinterpret_cast<float4*>(g_h   + (size_t)SPLIT_ROW0 * H_DIM + idx * 4) = z;
    *reinterpret_cast<float4*>(g_agg + (size_t)SPLIT_ROW0 * H_DIM + idx * 4) = z;
}

// ---------------------------------------------------------------------------
// GEMM1, tf32 HMMA + cp.async 4-stage pipeline, wave-balanced decomposition:
//   bid 0..147   : full tiles 0..147, chunks [0,545), direct-store epilogue
//   bid 148..291 : tiles 148..156 split-K x16, ~34 chunks, red.add epilogue
// BM=128, BN=128, BK=16, 256 threads = 8 warps (4m x 2n), warp tile 32x64
// ---------------------------------------------------------------------------
#define NC_CHUNKS ((K_IN + 15) / 16)   // 545
#define G1_STAGES 4
#define G1_BM 128
#define G1_BK 16
#define N_FULL    148
#define N_SPLITS  16                   // k-slices per split tile
#define A_STRIDE 20
#define B_STRIDE 136
#define A_WORDS (G1_BM * A_STRIDE)                   // 2560
#define STAGE_WORDS (A_WORDS + G1_BK * B_STRIDE)     // 4736
#define G1_SMEM_BYTES (G1_STAGES * STAGE_WORDS * 4)  // 75776
#define TRUNC_COMP 1.00034f

__device__ __forceinline__ unsigned smem_u32(const void* p) {
    unsigned a;
    asm("{ .reg .u64 t; cvta.to.shared.u64 t, %1; cvt.u32.u64 %0, t; }"
        : "=r"(a) : "l"(p));
    return a;
}

__global__ __launch_bounds__(256, 2) void k_gemm1_tc(const float* __restrict__ X) {
    extern __shared__ float sm[];

    const int tid  = threadIdx.x;
    const int warp = tid >> 5;
    const int lane = tid & 31;
    const int gid  = lane >> 2;     // 0..7
    const int tig  = lane & 3;      // 0..3
    const int warp_m = warp >> 1;   // 0..3
    const int warp_n = warp & 1;    // 0..1
    const unsigned sm_base = smem_u32(sm);

    // ---- work assignment ----
    int tile, c0, c_end;
    bool direct;
    if (blockIdx.x < N_FULL) {
        tile = blockIdx.x; c0 = 0; c_end = NC_CHUNKS; direct = true;
    } else {
        int t = blockIdx.x - N_FULL;
        tile = N_FULL + t / N_SPLITS;
        int s = t % N_SPLITS;
        const int base = NC_CHUNKS / N_SPLITS;           // 34
        const int rem  = NC_CHUNKS % N_SPLITS;           // 1
        c0    = s * base + (s < rem ? s : rem);
        c_end = c0 + base + (s < rem ? 1 : 0);
        direct = false;
    }
    const int m0 = tile * G1_BM;

    float acc[2][8][4];
#pragma unroll
    for (int i = 0; i < 2; i++)
#pragma unroll
        for (int j = 0; j < 8; j++)
#pragma unroll
            for (int t = 0; t < 4; t++) acc[i][j][t] = 0.f;

#define LOAD_STAGE(c)                                                             \
    {                                                                             \
        const int stg = (c) % G1_STAGES;                                          \
        const unsigned a_u = sm_base + stg * (STAGE_WORDS * 4);                   \
        const unsigned b_u = a_u + A_WORDS * 4;                                   \
        const int k0 = (c) * G1_BK;                                               \
        const bool inr = (c) < c_end;                                             \
        _Pragma("unroll")                                                         \
        for (int i = 0; i < 4; i++) {                                             \
            int p = tid + i * 256;                                                \
            int row = p >> 3;                                                     \
            int kp  = (p & 7) * 2;                                                \
            int gm = m0 + row, gk = k0 + kp;                                      \
            int ok = (inr && gm < N_NODES && gk + 1 < K_IN) ? 8 : 0;              \
            int gmc = gm < N_NODES ? gm : N_NODES - 1;                            \
            int gkc = gk + 1 < K_IN ? gk : 0;                                     \
            const float* src = X + (size_t)gmc * K_IN + gkc;                      \
            unsigned dst = a_u + (row * A_STRIDE + kp) * 4;                       \
            asm volatile("cp.async.ca.shared.global [%0], [%1], 8, %2;"           \
                         :: "r"(dst), "l"(src), "r"(ok));                         \
        }                                                                         \
        _Pragma("unroll")                                                         \
        for (int i = 0; i < 2; i++) {                                             \
            int q = tid + i * 256;                                                \
            int kr = q >> 5;                                                      \
            int nc = (q & 31) * 4;                                                \
            int gk = k0 + kr;                                                     \
            int ok = (inr && gk < K_IN) ? 16 : 0;                                 \
            int gkc = gk < K_IN ? gk : 0;                                         \
            const float* src = g_Wr + (size_t)gkc * H_DIM + nc;                   \
            unsigned dst = b_u + (kr * B_STRIDE + nc) * 4;                        \
            asm volatile("cp.async.cg.shared.global [%0], [%1], 16, %2;"          \
                         :: "r"(dst), "l"(src), "r"(ok));                         \
        }                                                                         \
        asm volatile("cp.async.commit_group;");                                   \
    }

    LOAD_STAGE(c0);
    LOAD_STAGE(c0 + 1);
    LOAD_STAGE(c0 + 2);

    for (int c = c0; c < c_end; ++c) {
        asm volatile("cp.async.wait_group %0;" :: "n"(G1_STAGES - 2));
        __syncthreads();

        LOAD_STAGE(c + G1_STAGES - 1);

        const unsigned* As = reinterpret_cast<const unsigned*>(
            sm + (c % G1_STAGES) * STAGE_WORDS);
        const unsigned* Bs = As + A_WORDS;

#pragma unroll
        for (int ks = 0; ks < 2; ks++) {
            const int kb = ks * 8;
            unsigned af[2][4];
#pragma unroll
            for (int mt = 0; mt < 2; mt++) {
                int r = warp_m * 32 + mt * 16 + gid;
                af[mt][0] = As[r * A_STRIDE + kb + tig];
                af[mt][1] = As[(r + 8) * A_STRIDE + kb + tig];
                af[mt][2] = As[r * A_STRIDE + kb + tig + 4];
                af[mt][3] = As[(r + 8) * A_STRIDE + kb + tig + 4];
            }
            unsigned bf[8][2];
#pragma unroll
            for (int nt = 0; nt < 8; nt++) {
                int nb = warp_n * 64 + nt * 8 + gid;
                bf[nt][0] = Bs[(kb + tig) * B_STRIDE + nb];
                bf[nt][1] = Bs[(kb + tig + 4) * B_STRIDE + nb];
            }
#pragma unroll
            for (int mt = 0; mt < 2; mt++)
#pragma unroll
                for (int nt = 0; nt < 8; nt++) {
                    asm volatile(
                        "mma.sync.aligned.m16n8k8.row.col.f32.tf32.tf32.f32 "
                        "{%0,%1,%2,%3}, {%4,%5,%6,%7}, {%8,%9}, {%0,%1,%2,%3};"
                        : "+f"(acc[mt][nt][0]), "+f"(acc[mt][nt][1]),
                          "+f"(acc[mt][nt][2]), "+f"(acc[mt][nt][3])
                        : "r"(af[mt][0]), "r"(af[mt][1]), "r"(af[mt][2]), "r"(af[mt][3]),
                          "r"(bf[nt][0]), "r"(bf[nt][1]));
                }
        }
    }
#undef LOAD_STAGE

    // epilogue: truncation compensation + fused agg-init (g_agg = h * dinv^2)
#pragma unroll
    for (int mt = 0; mt < 2; mt++) {
        int r0 = m0 + warp_m * 32 + mt * 16 + gid;
        int r1 = r0 + 8;
        float s0 = 0.f, s1 = 0.f;
        if (r0 < N_NODES) { float dv = g_dinv[r0]; s0 = dv * dv; }
        if (r1 < N_NODES) { float dv = g_dinv[r1]; s1 = dv * dv; }
#pragma unroll
        for (int nt = 0; nt < 8; nt++) {
            int col = warp_n * 64 + nt * 8 + tig * 2;
            float h0 = acc[mt][nt][0] * TRUNC_COMP;
            float h1 = acc[mt][nt][1] * TRUNC_COMP;
            float h2 = acc[mt][nt][2] * TRUNC_COMP;
            float h3 = acc[mt][nt][3] * TRUNC_COMP;
            if (direct) {
                if (r0 < N_NODES) {
                    *reinterpret_cast<float2*>(g_h + (size_t)r0 * H_DIM + col) =
                        make_float2(h0, h1);
                    *reinterpret_cast<float2*>(g_agg + (size_t)r0 * H_DIM + col) =
                        make_float2(h0 * s0, h1 * s0);
                }
                if (r1 < N_NODES) {
                    *reinterpret_cast<float2*>(g_h + (size_t)r1 * H_DIM + col) =
                        make_float2(h2, h3);
                    *reinterpret_cast<float2*>(g_agg + (size_t)r1 * H_DIM + col) =
                        make_float2(h2 * s1, h3 * s1);
                }
            } else {
                if (r0 < N_NODES) {
                    asm volatile("red.global.add.v2.f32 [%0], {%1,%2};"
                                 :: "l"(g_h + (size_t)r0 * H_DIM + col),
                                    "f"(h0), "f"(h1) : "memory");
                    asm volatile("red.global.add.v2.f32 [%0], {%1,%2};"
                                 :: "l"(g_agg + (size_t)r0 * H_DIM + col),
                                    "f"(h0 * s0), "f"(h1 * s0) : "memory");
                }
                if (r1 < N_NODES) {
                    asm volatile("red.global.add.v2.f32 [%0], {%1,%2};"
                                 :: "l"(g_h + (size_t)r1 * H_DIM + col),
                                    "f"(h2), "f"(h3) : "memory");
                    asm volatile("red.global.add.v2.f32 [%0], {%1,%2};"
                                 :: "l"(g_agg + (size_t)r1 * H_DIM + col),
                                    "f"(h2 * s1), "f"(h3 * s1) : "memory");
                }
            }
        }
    }
}

// ---------------------------------------------------------------------------
// layer-1 aggregation (agg init fused into gemm1 epilogue)
// ---------------------------------------------------------------------------
__global__ void k_scatter1(const int* __restrict__ edges, int E) {
    int idx = blockIdx.x * blockDim.x + threadIdx.x;   // E*32 (edge, col4)
    if (idx >= E * 32) return;
    int e = idx >> 5;
    int g = idx & 31;
    int s = edges[e];
    int d = edges[E + e];
    float norm = g_dinv[s] * g_dinv[d];
    float4 v = *reinterpret_cast<const float4*>(g_h + (size_t)s * H_DIM + g * 4);
    float* p = g_agg + (size_t)d * H_DIM + g * 4;
    asm volatile("red.global.add.v4.f32 [%0], {%1,%2,%3,%4};"
                 :: "l"(p), "f"(v.x * norm), "f"(v.y * norm),
                    "f"(v.z * norm), "f"(v.w * norm)
                 : "memory");
}

__global__ void k_bias_relu(const float* __restrict__ b1) {
    int idx = blockIdx.x * blockDim.x + threadIdx.x;   // N*32 float4 slots
    if (idx >= N_NODES * 32) return;
    int j4 = (idx & 31) * 4;
    float4 b = *reinterpret_cast<const float4*>(b1 + j4);
    float4 v = *reinterpret_cast<const float4*>(g_agg + (size_t)idx * 4);
    v.x = fmaxf(v.x + b.x, 0.f);
    v.y = fmaxf(v.y + b.y, 0.f);
    v.z = fmaxf(v.z + b.z, 0.f);
    v.w = fmaxf(v.w + b.w, 0.f);
    *reinterpret_cast<float4*>(g_h + (size_t)idx * 4) = v;
}

// ---------------------------------------------------------------------------
// GEMM2: z = h1 @ W2   [20000 x 128] @ [128 x 70] — warp per row
// ---------------------------------------------------------------------------
__global__ __launch_bounds__(256) void k_gemm2(const float* __restrict__ W2) {
    __shared__ float W2s[H_DIM * C_DIM];   // 35840 B
    int tid = threadIdx.x;
    for (int i = tid; i < H_DIM * C_DIM; i += 256) W2s[i] = W2[i];
    __syncthreads();

    int warp = tid >> 5, lane = tid & 31;
    int n = blockIdx.x * 8 + warp;
    if (n >= N_NODES) return;
    const float* hr = g_h + (size_t)n * H_DIM;

    float a0 = 0.f, a1 = 0.f, a2 = 0.f;
#pragma unroll 4
    for (int k = 0; k < H_DIM; k++) {
        float hv = __ldg(hr + k);                  // uniform per warp
        const float* wr = W2s + k * C_DIM;
        a0 += hv * wr[lane];
        a1 += hv * wr[lane + 32];
        if (lane < C_DIM - 64) a2 += hv * wr[lane + 64];
    }
    float* zr = g_z + (size_t)n * C_DIM;
    zr[lane]      = a0;
    zr[lane + 32] = a1;
    if (lane < C_DIM - 64) zr[lane + 64] = a2;
}

// ---------------------------------------------------------------------------
// layer-2 aggregation (into d_out) + softmax
// ---------------------------------------------------------------------------
__global__ void k_agg2_init(float* __restrict__ out) {
    int idx = blockIdx.x * blockDim.x + threadIdx.x;   // N*70
    if (idx >= N_NODES * C_DIM) return;
    int n = idx / C_DIM;
    float s = g_dinv[n]; s = s * s;
    out[idx] = g_z[idx] * s;
}

__global__ void k_scatter2(const int* __restrict__ edges, int E,
                           float* __restrict__ out) {
    int idx = blockIdx.x * blockDim.x + threadIdx.x;   // E*32: warp per edge
    if (idx >= E * 32) return;
    int e = idx >> 5;
    int lane = idx & 31;
    int s = edges[e];
    int d = edges[E + e];
    float norm = g_dinv[s] * g_dinv[d];
    const float* zr = g_z + (size_t)s * C_DIM;
    float* orow = out + (size_t)d * C_DIM;

    {   // pairs 0..31 -> cols 0..63
        float2 v = *reinterpret_cast<const float2*>(zr + 2 * lane);
        asm volatile("red.global.add.v2.f32 [%0], {%1,%2};"
                     :: "l"(orow + 2 * lane), "f"(v.x * norm), "f"(v.y * norm)
                     : "memory");
    }
    if (lane < 3) {   // pairs 32..34 -> cols 64..69
        float2 v = *reinterpret_cast<const float2*>(zr + 64 + 2 * lane);
        asm volatile("red.global.add.v2.f32 [%0], {%1,%2};"
                     :: "l"(orow + 64 + 2 * lane), "f"(v.x * norm), "f"(v.y * norm)
                     : "memory");
    }
}

__global__ __launch_bounds__(256) void k_softmax(const float* __restrict__ b2,
                                                 float* __restrict__ out) {
    int warp = threadIdx.x >> 5, lane = threadIdx.x & 31;
    int n = blockIdx.x * 8 + warp;
    if (n >= N_NODES) return;
    float* r = out + (size_t)n * C_DIM;

    float v0 = r[lane] + b2[lane];
    float v1 = r[lane + 32] + b2[lane + 32];
    float v2 = (lane < C_DIM - 64) ? r[lane + 64] + b2[lane + 64] : -INFINITY;

    float m = fmaxf(fmaxf(v0, v1), v2);
#pragma unroll
    for (int o = 16; o > 0; o >>= 1) m = fmaxf(m, __shfl_xor_sync(0xffffffff, m, o));

    float e0 = expf(v0 - m);
    float e1 = expf(v1 - m);
    float e2 = (lane < C_DIM - 64) ? expf(v2 - m) : 0.f;
    float s = e0 + e1 + e2;
#pragma unroll
    for (int o = 16; o > 0; o >>= 1) s += __shfl_xor_sync(0xffffffff, s, o);
    float inv = 1.f / s;

    r[lane]      = e0 * inv;
    r[lane + 32] = e1 * inv;
    if (lane < C_DIM - 64) r[lane + 64] = e2 * inv;
}

// ---------------------------------------------------------------------------
extern "C" void kernel_launch(void* const* d_in, const int* in_sizes, int n_in,
                              void* d_out, int out_size) {
    const float* x  = (const float*)d_in[0];
    const int* edges = (const int*)d_in[1];
    const float* W1 = (const float*)d_in[2];
    const float* b1 = (const float*)d_in[3];
    const float* W2 = (const float*)d_in[4];
    const float* b2 = (const float*)d_in[5];
    float* out = (float*)d_out;
    const int E = in_sizes[1] / 2;

    cudaFuncSetAttribute(k_gemm1_tc, cudaFuncAttributeMaxDynamicSharedMemorySize,
                         G1_SMEM_BYTES);

    // degree / dinv + weight pre-rounding + split-tile zero-init
    k_zero_deg<<<(N_NODES + 255) / 256, 256>>>();
    k_count_deg<<<(E + 255) / 256, 256>>>(edges, E);
    k_dinv<<<(N_NODES + 255) / 256, 256>>>();
    k_round_w<<<(K_IN * H_DIM + 255) / 256, 256>>>(W1);
    k_zero_tail<<<((N_NODES - SPLIT_ROW0) * 32 + 255) / 256, 256>>>();

    // layer 1: 148 full tiles + 9 tiles split-K x16 = 292 CTAs (one wave)
    k_gemm1_tc<<<N_FULL + (157 - N_FULL) * N_SPLITS, 256, G1_SMEM_BYTES>>>(x);
    k_scatter1<<<(E * 32 + 255) / 256, 256>>>(edges, E);
    k_bias_relu<<<(N_NODES * 32 + 255) / 256, 256>>>(b1);

    // layer 2
    k_gemm2<<<(N_NODES + 7) / 8, 256>>>(W2);
    k_agg2_init<<<(N_NODES * C_DIM + 255) / 256, 256>>>(out);
    k_scatter2<<<(E * 32 + 255) / 256, 256>>>(edges, E, out);
    k_softmax<<<(N_NODES + 7) / 8, 256>>>(b2, out);
}